// round 1
// baseline (speedup 1.0000x reference)
#include <cuda_runtime.h>

#define BB 4
#define TT 2048
#define DDIM 512
#define HH 8
#define DK 64

// Scratch (allocation-free: __device__ globals)
__device__ float g_q[(size_t)BB * HH * TT * DK];
__device__ float g_k[(size_t)BB * HH * TT * DK];
__device__ float g_v[(size_t)BB * HH * TT * DK];
__device__ float g_ctx[(size_t)BB * TT * DDIM];

// ---------------------------------------------------------------------------
// Generic fp32 GEMM core. C[M,N] = A[M,K] * op(B).
// BT=true:  B is [N,K] row-major (NT gemm, i.e. A @ B^T)
// BT=false: B is [K,N] row-major (NN gemm)
// 256 threads. Register tile TM x TN per thread. Smem padded +4 floats so
// float4 LDS stays 16B-aligned (row stride BM+4 / BN+4 is a multiple of 4).
// ---------------------------------------------------------------------------
template <int BM, int BN, int BK, int TM, int TN, bool BT>
__device__ __forceinline__ void gemm_core(
    const float* __restrict__ A, int lda,
    const float* __restrict__ B, int ldb,
    int K, int tile_m, int tile_n,
    float acc[TM][TN])
{
    __shared__ float As[BK][BM + 4];
    __shared__ float Bs[BK][BN + 4];

    const int tid = threadIdx.x;
    constexpr int NTX = BN / TN;
    const int tx = tid % NTX;
    const int ty = tid / NTX;

    for (int k0 = 0; k0 < K; k0 += BK) {
        // Load A tile (transposed into smem: As[k][m])
        #pragma unroll
        for (int idx = tid; idx < BM * BK; idx += 256) {
            int r = idx / BK, c = idx % BK;
            As[c][r] = A[(size_t)(tile_m + r) * lda + k0 + c];
        }
        if (BT) {
            #pragma unroll
            for (int idx = tid; idx < BN * BK; idx += 256) {
                int r = idx / BK, c = idx % BK;
                Bs[c][r] = B[(size_t)(tile_n + r) * ldb + k0 + c];
            }
        } else {
            #pragma unroll
            for (int idx = tid; idx < BN * BK; idx += 256) {
                int kk = idx / BN, n = idx % BN;
                Bs[kk][n] = B[(size_t)(k0 + kk) * ldb + tile_n + n];
            }
        }
        __syncthreads();

        #pragma unroll
        for (int kk = 0; kk < BK; kk++) {
            float a[TM], b[TN];
            #pragma unroll
            for (int i = 0; i < TM; i += 4) {
                float4 t = *(const float4*)&As[kk][ty * TM + i];
                a[i] = t.x; a[i + 1] = t.y; a[i + 2] = t.z; a[i + 3] = t.w;
            }
            #pragma unroll
            for (int j = 0; j < TN; j += 4) {
                float4 t = *(const float4*)&Bs[kk][tx * TN + j];
                b[j] = t.x; b[j + 1] = t.y; b[j + 2] = t.z; b[j + 3] = t.w;
            }
            #pragma unroll
            for (int i = 0; i < TM; i++)
                #pragma unroll
                for (int j = 0; j < TN; j++)
                    acc[i][j] = fmaf(a[i], b[j], acc[i][j]);
        }
        __syncthreads();
    }
}

// ---------------------------------------------------------------------------
// Kernel 1: QKV projection. out = X @ W^T + b, scattered to [B,H,T,DK].
// M=8192 (B*T), N=512, K=512. BM=128, BN=64, TM=8, TN=4.
// dst: 0 -> g_q, 1 -> g_k, 2 -> g_v
// ---------------------------------------------------------------------------
__global__ __launch_bounds__(256, 2) void proj_kernel(
    const float* __restrict__ X, const float* __restrict__ W,
    const float* __restrict__ bias, int dst)
{
    constexpr int BM = 128, BN = 64, BK = 16, TM = 8, TN = 4;
    int tile_m = blockIdx.y * BM;
    int tile_n = blockIdx.x * BN;
    float acc[TM][TN] = {};
    gemm_core<BM, BN, BK, TM, TN, true>(X, DDIM, W, DDIM, DDIM, tile_m, tile_n, acc);

    float* dstp = (dst == 0) ? g_q : (dst == 1) ? g_k : g_v;
    const int tx = threadIdx.x % (BN / TN);
    const int ty = threadIdx.x / (BN / TN);
    #pragma unroll
    for (int i = 0; i < TM; i++) {
        int m = tile_m + ty * TM + i;
        int b = m >> 11;          // / TT
        int t = m & (TT - 1);
        #pragma unroll
        for (int j = 0; j < TN; j++) {
            int n = tile_n + tx * TN + j;
            int h = n >> 6;       // / DK
            int dk = n & (DK - 1);
            float val = acc[i][j] + bias[n];
            dstp[((((size_t)b * HH + h) * TT + t) << 6) + dk] = val;
        }
    }
}

// ---------------------------------------------------------------------------
// Kernel 2: energy = (q @ k^T) / 8, masked -> written into aw region of d_out.
// Per (b,h): M=N=2048, K=64. BM=BN=128, TM=TN=8.
// ---------------------------------------------------------------------------
__global__ __launch_bounds__(256, 2) void energy_kernel(
    const int* __restrict__ mask, float* __restrict__ aw)
{
    constexpr int BM = 128, BN = 128, BK = 16, TM = 8, TN = 8;
    int bh = blockIdx.z;
    const float* A = g_q + (size_t)bh * TT * DK;
    const float* Bm = g_k + (size_t)bh * TT * DK;
    int tile_m = blockIdx.y * BM;
    int tile_n = blockIdx.x * BN;
    float acc[TM][TN] = {};
    gemm_core<BM, BN, BK, TM, TN, true>(A, DK, Bm, DK, DK, tile_m, tile_n, acc);

    int b = bh >> 3;  // / HH
    float* awp = aw + (size_t)bh * TT * TT;
    const int tx = threadIdx.x % (BN / TN);
    const int ty = threadIdx.x / (BN / TN);
    #pragma unroll
    for (int i = 0; i < TM; i++) {
        int tq = tile_m + ty * TM + i;
        const int* mrow = mask + ((size_t)b * TT + tq) * TT;
        #pragma unroll
        for (int j = 0; j < TN; j++) {
            int tk = tile_n + tx * TN + j;
            float e = acc[i][j] * 0.125f;
            if (mrow[tk] == 0) e = -1024.0f;
            awp[(size_t)tq * TT + tk] = e;
        }
    }
}

// ---------------------------------------------------------------------------
// Kernel 3: row softmax in place on aw. One block per row of 2048.
// ---------------------------------------------------------------------------
__global__ __launch_bounds__(256) void softmax_kernel(float* __restrict__ aw)
{
    __shared__ float redm[8];
    __shared__ float reds[8];
    size_t row = blockIdx.x;
    float* p = aw + row * (size_t)TT;
    int tid = threadIdx.x;
    int lane = tid & 31, wid = tid >> 5;

    float v[8];
    float mx = -3.0e38f;
    #pragma unroll
    for (int i = 0; i < 8; i++) {
        v[i] = p[tid + (i << 8)];
        mx = fmaxf(mx, v[i]);
    }
    #pragma unroll
    for (int o = 16; o > 0; o >>= 1)
        mx = fmaxf(mx, __shfl_xor_sync(0xffffffffu, mx, o));
    if (lane == 0) redm[wid] = mx;
    __syncthreads();
    float bm = redm[0];
    #pragma unroll
    for (int i = 1; i < 8; i++) bm = fmaxf(bm, redm[i]);

    float s = 0.0f;
    #pragma unroll
    for (int i = 0; i < 8; i++) {
        v[i] = __expf(v[i] - bm);
        s += v[i];
    }
    #pragma unroll
    for (int o = 16; o > 0; o >>= 1)
        s += __shfl_xor_sync(0xffffffffu, s, o);
    if (lane == 0) reds[wid] = s;
    __syncthreads();
    float bs = reds[0];
    #pragma unroll
    for (int i = 1; i < 8; i++) bs += reds[i];

    float inv = 1.0f / bs;
    #pragma unroll
    for (int i = 0; i < 8; i++)
        p[tid + (i << 8)] = v[i] * inv;
}

// ---------------------------------------------------------------------------
// Kernel 4: context = aw @ v, per (b,h). M=2048, N=64, K=2048 (NN gemm).
// Written to g_ctx in [B,T,D] layout (heads merged).
// ---------------------------------------------------------------------------
__global__ __launch_bounds__(256, 2) void av_kernel(const float* __restrict__ aw)
{
    constexpr int BM = 128, BN = 64, BK = 16, TM = 8, TN = 4;
    int bh = blockIdx.z;
    const float* A = aw + (size_t)bh * TT * TT;    // [T, T]
    const float* V = g_v + (size_t)bh * TT * DK;   // [T, DK]
    int tile_m = blockIdx.y * BM;
    int tile_n = 0;  // BN == N == 64
    float acc[TM][TN] = {};
    gemm_core<BM, BN, BK, TM, TN, false>(A, TT, V, DK, TT, tile_m, tile_n, acc);

    int b = bh >> 3, h = bh & 7;
    const int tx = threadIdx.x % (BN / TN);
    const int ty = threadIdx.x / (BN / TN);
    #pragma unroll
    for (int i = 0; i < TM; i++) {
        int tq = tile_m + ty * TM + i;
        float* crow = g_ctx + ((size_t)b * TT + tq) * DDIM + h * DK;
        #pragma unroll
        for (int j = 0; j < TN; j++) {
            int n = tx * TN + j;
            crow[n] = acc[i][j];
        }
    }
}

// ---------------------------------------------------------------------------
// Kernel 5: output projection. out = ctx @ Wo^T + bo -> context region of d_out.
// ---------------------------------------------------------------------------
__global__ __launch_bounds__(256, 2) void outproj_kernel(
    const float* __restrict__ Wo, const float* __restrict__ bo,
    float* __restrict__ out)
{
    constexpr int BM = 128, BN = 64, BK = 16, TM = 8, TN = 4;
    int tile_m = blockIdx.y * BM;
    int tile_n = blockIdx.x * BN;
    float acc[TM][TN] = {};
    gemm_core<BM, BN, BK, TM, TN, true>(g_ctx, DDIM, Wo, DDIM, DDIM, tile_m, tile_n, acc);

    const int tx = threadIdx.x % (BN / TN);
    const int ty = threadIdx.x / (BN / TN);
    #pragma unroll
    for (int i = 0; i < TM; i++) {
        int m = tile_m + ty * TM + i;
        #pragma unroll
        for (int j = 0; j < TN; j++) {
            int n = tile_n + tx * TN + j;
            out[(size_t)m * DDIM + n] = acc[i][j] + bo[n];
        }
    }
}

// ---------------------------------------------------------------------------
extern "C" void kernel_launch(void* const* d_in, const int* in_sizes, int n_in,
                              void* d_out, int out_size)
{
    const float* key   = (const float*)d_in[0];
    const float* value = (const float*)d_in[1];
    const float* query = (const float*)d_in[2];
    const int*   mask  = (const int*)d_in[3];
    const float* Wk = (const float*)d_in[4];
    const float* bk = (const float*)d_in[5];
    const float* Wv = (const float*)d_in[6];
    const float* bv = (const float*)d_in[7];
    const float* Wq = (const float*)d_in[8];
    const float* bq = (const float*)d_in[9];
    const float* Wo = (const float*)d_in[10];
    const float* bo = (const float*)d_in[11];

    float* out = (float*)d_out;
    float* ctx_out = out;                                    // [B, T, D]
    float* aw_out  = out + (size_t)BB * TT * DDIM;           // [B, H, T, T]

    // 1. QKV projections (M=8192, N=512)
    dim3 gproj(DDIM / 64, (BB * TT) / 128);
    proj_kernel<<<gproj, 256>>>(query, Wq, bq, 0);
    proj_kernel<<<gproj, 256>>>(key,   Wk, bk, 1);
    proj_kernel<<<gproj, 256>>>(value, Wv, bv, 2);

    // 2. energy (masked, scaled) -> aw region
    dim3 genergy(TT / 128, TT / 128, BB * HH);
    energy_kernel<<<genergy, 256>>>(mask, aw_out);

    // 3. softmax in-place on aw
    softmax_kernel<<<BB * HH * TT, 256>>>(aw_out);

    // 4. context = aw @ v
    dim3 gav(1, TT / 128, BB * HH);
    av_kernel<<<gav, 256>>>(aw_out);

    // 5. output projection
    dim3 gout(DDIM / 64, (BB * TT) / 128);
    outproj_kernel<<<gout, 256>>>(Wo, bo, ctx_out);
}

// round 4
// speedup vs baseline: 2.1492x; 2.1492x over previous
#include <cuda_runtime.h>
#include <cuda_bf16.h>
#include <cstdint>

typedef unsigned int u32;

#define BB 4
#define TT 2048
#define DDIM 512
#define HH 8
#define DKH 64

#define SZQ ((size_t)BB * HH * TT * DKH)   // 4,194,304
#define SZX ((size_t)BB * TT * DDIM)       // 4,194,304

// ---------------- scratch (__device__ globals; no allocation) ----------------
__device__ __nv_bfloat16 g_xh[3][SZX], g_xl[3][SZX];          // q/k/v inputs
__device__ __nv_bfloat16 g_wh[4][DDIM * DDIM], g_wl[4][DDIM * DDIM];
__device__ __nv_bfloat16 g_qh[SZQ], g_ql[SZQ];                // [B,H,T,DK]
__device__ __nv_bfloat16 g_kh[SZQ], g_kl[SZQ];                // [B,H,T,DK]
__device__ __nv_bfloat16 g_vh[SZQ], g_vl[SZQ];                // [B,H,T,DK]
__device__ __nv_bfloat16 g_ch[SZX], g_cl[SZX];                // ctx [B,T,D]
__device__ u32 g_mbits[(size_t)BB * TT * (TT / 32)];          // packed mask bits

// ---------------- small helpers ----------------
__device__ __forceinline__ u32 smem_u32(const void* p) {
    u32 a;
    asm("{ .reg .u64 t; cvta.to.shared.u64 t, %1; cvt.u32.u64 %0, t; }" : "=r"(a) : "l"(p));
    return a;
}
__device__ __forceinline__ void split_hl(float v, __nv_bfloat16& h, __nv_bfloat16& l) {
    h = __float2bfloat16(v);
    l = __float2bfloat16(v - __bfloat162float(h));
}
__device__ __forceinline__ u32 pack2(__nv_bfloat16 a, __nv_bfloat16 b) {
    return (u32)__bfloat16_as_ushort(a) | ((u32)__bfloat16_as_ushort(b) << 16);
}

__device__ __forceinline__ void ldsm_x4(u32& r0, u32& r1, u32& r2, u32& r3, u32 addr) {
    asm volatile("ldmatrix.sync.aligned.m8n8.x4.shared.b16 {%0,%1,%2,%3}, [%4];"
                 : "=r"(r0), "=r"(r1), "=r"(r2), "=r"(r3) : "r"(addr));
}
__device__ __forceinline__ void mma16816(float* c, const u32* a, u32 b0, u32 b1) {
    asm volatile(
        "mma.sync.aligned.m16n8k16.row.col.f32.bf16.bf16.f32 "
        "{%0,%1,%2,%3}, {%4,%5,%6,%7}, {%8,%9}, {%0,%1,%2,%3};"
        : "+f"(c[0]), "+f"(c[1]), "+f"(c[2]), "+f"(c[3])
        : "r"(a[0]), "r"(a[1]), "r"(a[2]), "r"(a[3]), "r"(b0), "r"(b1));
}

#define BKP 40  // 32 + 8 pad (80B row stride -> conflict-free ldmatrix)

// ---------------- smem tile loaders ----------------
// bf16 hi/lo source [rows][ld], load ROWS x 32 elems at (row0, k0)
template <int ROWS>
__device__ __forceinline__ void load_hl(
    __nv_bfloat16 (*sh)[BKP], __nv_bfloat16 (*sl)[BKP],
    const __nv_bfloat16* __restrict__ gh, const __nv_bfloat16* __restrict__ gl,
    size_t ld, size_t row0, int k0, int tid)
{
    #pragma unroll
    for (int i = tid; i < ROWS * 8; i += 256) {
        int r = i >> 3, c = i & 7;
        int cc = (c & 3) * 8;
        if (c < 4)
            *(uint4*)&sh[r][cc] = *(const uint4*)&gh[(row0 + (size_t)r) * ld + k0 + cc];
        else
            *(uint4*)&sl[r][cc] = *(const uint4*)&gl[(row0 + (size_t)r) * ld + k0 + cc];
    }
}

// fp32 source [rows][ld] -> hi/lo bf16 tiles (ROWS x 32)
template <int ROWS>
__device__ __forceinline__ void load_f32_hl(
    __nv_bfloat16 (*sh)[BKP], __nv_bfloat16 (*sl)[BKP],
    const float* __restrict__ g, size_t ld, size_t row0, int k0, int tid)
{
    #pragma unroll
    for (int i = tid; i < ROWS * 8; i += 256) {
        int r = i >> 3, c = i & 7;
        float4 v = *(const float4*)&g[(row0 + (size_t)r) * ld + k0 + c * 4];
        __nv_bfloat16 h0, l0, h1, l1, h2, l2, h3, l3;
        split_hl(v.x, h0, l0); split_hl(v.y, h1, l1);
        split_hl(v.z, h2, l2); split_hl(v.w, h3, l3);
        uint2 ph = make_uint2(pack2(h0, h1), pack2(h2, h3));
        uint2 pl = make_uint2(pack2(l0, l1), pack2(l2, l3));
        *(uint2*)&sh[r][c * 4] = ph;
        *(uint2*)&sl[r][c * 4] = pl;
    }
}

// v transpose loader: src [T][64] hi/lo rows row0..row0+31 -> dst [64][BKP] (n=dk, k=t)
__device__ __forceinline__ void load_v_trans(
    __nv_bfloat16 (*sh)[BKP], __nv_bfloat16 (*sl)[BKP],
    const __nv_bfloat16* __restrict__ gh, const __nv_bfloat16* __restrict__ gl,
    size_t row0, int tid)
{
    #pragma unroll
    for (int i = tid; i < 256; i += 256) {
        int tr = i >> 3, c = i & 7;
        uint4 vh = *(const uint4*)&gh[(row0 + (size_t)tr) * DKH + c * 8];
        uint4 vl = *(const uint4*)&gl[(row0 + (size_t)tr) * DKH + c * 8];
        const __nv_bfloat16* ph = (const __nv_bfloat16*)&vh;
        const __nv_bfloat16* pl = (const __nv_bfloat16*)&vl;
        #pragma unroll
        for (int j = 0; j < 8; j++) {
            sh[c * 8 + j][tr] = ph[j];
            sl[c * 8 + j][tr] = pl[j];
        }
    }
}

// ---------------- warp-MMA compute over one BK=32 tile ----------------
template <int MFRAGS, int NFRAGS>
__device__ __forceinline__ void mma_compute(
    const __nv_bfloat16 (*Ah)[BKP], const __nv_bfloat16 (*Al)[BKP],
    const __nv_bfloat16 (*Bh)[BKP], const __nv_bfloat16 (*Bl)[BKP],
    int wrow, int wcol, int lane, float acc[MFRAGS][NFRAGS][4])
{
    const int arow = wrow + (lane & 15);
    const int akh = (lane >> 4) << 3;
    const int brow = wcol + (lane & 7) + ((lane & 16) >> 1);
    const int bkh = (lane & 8);
    #pragma unroll
    for (int ks = 0; ks < 32; ks += 16) {
        u32 ah[MFRAGS][4], al[MFRAGS][4];
        #pragma unroll
        for (int mf = 0; mf < MFRAGS; mf++) {
            ldsm_x4(ah[mf][0], ah[mf][1], ah[mf][2], ah[mf][3],
                    smem_u32(&Ah[arow + mf * 16][ks + akh]));
            ldsm_x4(al[mf][0], al[mf][1], al[mf][2], al[mf][3],
                    smem_u32(&Al[arow + mf * 16][ks + akh]));
        }
        #pragma unroll
        for (int np = 0; np < NFRAGS / 2; np++) {
            u32 bh0, bh1, bh2, bh3, bl0, bl1, bl2, bl3;
            ldsm_x4(bh0, bh1, bh2, bh3, smem_u32(&Bh[brow + np * 16][ks + bkh]));
            ldsm_x4(bl0, bl1, bl2, bl3, smem_u32(&Bl[brow + np * 16][ks + bkh]));
            #pragma unroll
            for (int mf = 0; mf < MFRAGS; mf++) {
                mma16816(acc[mf][2 * np],     ah[mf], bh0, bh1);
                mma16816(acc[mf][2 * np],     ah[mf], bl0, bl1);
                mma16816(acc[mf][2 * np],     al[mf], bh0, bh1);
                mma16816(acc[mf][2 * np + 1], ah[mf], bh2, bh3);
                mma16816(acc[mf][2 * np + 1], ah[mf], bl2, bl3);
                mma16816(acc[mf][2 * np + 1], al[mf], bh2, bh3);
            }
        }
    }
}

// ---------------- conversion kernels ----------------
__global__ __launch_bounds__(256) void cvt_x_kernel(const float* __restrict__ in, int slot)
{
    size_t i = (size_t)blockIdx.x * 256 + threadIdx.x;
    __nv_bfloat16 h, l;
    split_hl(in[i], h, l);
    g_xh[slot][i] = h;
    g_xl[slot][i] = l;
}
__global__ __launch_bounds__(256) void cvt_w_kernel(const float* __restrict__ in, int slot)
{
    size_t i = (size_t)blockIdx.x * 256 + threadIdx.x;
    __nv_bfloat16 h, l;
    split_hl(in[i], h, l);
    g_wh[slot][i] = h;
    g_wl[slot][i] = l;
}
__global__ __launch_bounds__(256) void cvt_mask_kernel(const int* __restrict__ mask)
{
    size_t i = (size_t)blockIdx.x * 256 + threadIdx.x;
    u32 bit = (mask[i] != 0) ? 1u : 0u;
    u32 word = __ballot_sync(0xffffffffu, bit);
    if ((threadIdx.x & 31) == 0) g_mbits[i >> 5] = word;
}

// ---------------- proj: out = X @ W^T + b -> q/k/v hi/lo [B,H,T,DK] ----------
__global__ __launch_bounds__(256, 2) void proj_mma(int xslot, int wslot,
                                                   const float* __restrict__ bias, int dst)
{
    __shared__ __nv_bfloat16 sAh[128][BKP], sAl[128][BKP];
    __shared__ __nv_bfloat16 sBh[128][BKP], sBl[128][BKP];
    const int tid = threadIdx.x, lane = tid & 31, wid = tid >> 5;
    const int wrow = (wid >> 1) * 32, wcol = (wid & 1) * 64;
    const int tile_m = blockIdx.y * 128, tile_n = blockIdx.x * 128;

    float acc[2][8][4] = {};
    for (int k0 = 0; k0 < DDIM; k0 += 32) {
        __syncthreads();
        load_hl<128>(sAh, sAl, g_xh[xslot], g_xl[xslot], DDIM, tile_m, k0, tid);
        load_hl<128>(sBh, sBl, g_wh[wslot], g_wl[wslot], DDIM, tile_n, k0, tid);
        __syncthreads();
        mma_compute<2, 8>(sAh, sAl, sBh, sBl, wrow, wcol, lane, acc);
    }

    __nv_bfloat16* dh = (dst == 0) ? g_qh : (dst == 1) ? g_kh : g_vh;
    __nv_bfloat16* dl = (dst == 0) ? g_ql : (dst == 1) ? g_kl : g_vl;
    const int r0 = tile_m + wrow + (lane >> 2);
    const int c0 = tile_n + wcol + (lane & 3) * 2;
    #pragma unroll
    for (int mf = 0; mf < 2; mf++)
        #pragma unroll
        for (int hf = 0; hf < 2; hf++) {
            int m = r0 + mf * 16 + hf * 8;
            int b = m >> 11, t = m & (TT - 1);
            #pragma unroll
            for (int nf = 0; nf < 8; nf++) {
                int n = c0 + nf * 8;
                float v0 = acc[mf][nf][hf * 2]     + bias[n];
                float v1 = acc[mf][nf][hf * 2 + 1] + bias[n + 1];
                int hh = n >> 6, dk = n & 63;
                size_t idx = ((size_t)(b * HH + hh) * TT + t) * DKH + dk;
                __nv_bfloat16 h0, l0, h1, l1;
                split_hl(v0, h0, l0);
                split_hl(v1, h1, l1);
                *(u32*)&dh[idx] = pack2(h0, h1);
                *(u32*)&dl[idx] = pack2(l0, l1);
            }
        }
}

// ---------------- energy: p = exp(mask ? qk/8 : -inf) -> aw region ----------
__global__ __launch_bounds__(256, 2) void energy_mma(float* __restrict__ aw)
{
    __shared__ __nv_bfloat16 sAh[128][BKP], sAl[128][BKP];
    __shared__ __nv_bfloat16 sBh[128][BKP], sBl[128][BKP];
    const int tid = threadIdx.x, lane = tid & 31, wid = tid >> 5;
    const int wrow = (wid >> 1) * 32, wcol = (wid & 1) * 64;
    const int bz = blockIdx.z;
    const size_t hbase = (size_t)bz * TT * DKH;
    const int tile_m = blockIdx.y * 128, tile_n = blockIdx.x * 128;

    float acc[2][8][4] = {};
    for (int k0 = 0; k0 < DKH; k0 += 32) {
        __syncthreads();
        load_hl<128>(sAh, sAl, g_qh + hbase, g_ql + hbase, DKH, tile_m, k0, tid);
        load_hl<128>(sBh, sBl, g_kh + hbase, g_kl + hbase, DKH, tile_n, k0, tid);
        __syncthreads();
        mma_compute<2, 8>(sAh, sAl, sBh, sBl, wrow, wcol, lane, acc);
    }

    const int b = bz >> 3;
    const int r0 = tile_m + wrow + (lane >> 2);
    const int c0 = tile_n + wcol + (lane & 3) * 2;
    #pragma unroll
    for (int mf = 0; mf < 2; mf++)
        #pragma unroll
        for (int hf = 0; hf < 2; hf++) {
            int tq = r0 + mf * 16 + hf * 8;
            const u32* mw = g_mbits + ((size_t)b * TT + tq) * (TT / 32);
            float* prow = aw + ((size_t)bz * TT + tq) * TT;
            #pragma unroll
            for (int nf = 0; nf < 8; nf++) {
                int tk = c0 + nf * 8;
                u32 w = mw[tk >> 5];
                int sh = tk & 31;
                float e0 = acc[mf][nf][hf * 2]     * 0.125f;
                float e1 = acc[mf][nf][hf * 2 + 1] * 0.125f;
                float2 p;
                p.x = ((w >> sh) & 1u)       ? __expf(e0) : 0.0f;
                p.y = ((w >> (sh + 1)) & 1u) ? __expf(e1) : 0.0f;
                *(float2*)&prow[tk] = p;
            }
        }
}

// ---------------- normalize: aw[row] /= sum(aw[row]) (deterministic) --------
__global__ __launch_bounds__(256) void norm_kernel(float* __restrict__ aw)
{
    __shared__ float reds[8];
    float* p = aw + (size_t)blockIdx.x * TT;
    const int tid = threadIdx.x, lane = tid & 31, wid = tid >> 5;

    float4 v0 = ((const float4*)p)[tid];
    float4 v1 = ((const float4*)p)[tid + 256];
    float s = v0.x + v0.y + v0.z + v0.w + v1.x + v1.y + v1.z + v1.w;
    #pragma unroll
    for (int o = 16; o > 0; o >>= 1) s += __shfl_xor_sync(0xffffffffu, s, o);
    if (lane == 0) reds[wid] = s;
    __syncthreads();
    float t = reds[0];
    #pragma unroll
    for (int i = 1; i < 8; i++) t += reds[i];
    float inv = 1.0f / t;
    v0.x *= inv; v0.y *= inv; v0.z *= inv; v0.w *= inv;
    v1.x *= inv; v1.y *= inv; v1.z *= inv; v1.w *= inv;
    ((float4*)p)[tid] = v0;
    ((float4*)p)[tid + 256] = v1;
}

// ---------------- av: ctx = aw @ v -> ctx hi/lo [B,T,D] ----------------------
__global__ __launch_bounds__(256, 2) void av_mma(const float* __restrict__ aw)
{
    __shared__ __nv_bfloat16 sAh[128][BKP], sAl[128][BKP];
    __shared__ __nv_bfloat16 sBh[64][BKP], sBl[64][BKP];
    const int tid = threadIdx.x, lane = tid & 31, wid = tid >> 5;
    const int wrow = wid * 16, wcol = 0;
    const int bz = blockIdx.z;
    const int tile_m = blockIdx.y * 128;
    const float* A = aw + (size_t)bz * TT * TT;
    const __nv_bfloat16* vh = g_vh + (size_t)bz * TT * DKH;
    const __nv_bfloat16* vl = g_vl + (size_t)bz * TT * DKH;

    float acc[1][8][4] = {};
    for (int k0 = 0; k0 < TT; k0 += 32) {
        __syncthreads();
        load_f32_hl<128>(sAh, sAl, A, TT, tile_m, k0, tid);
        load_v_trans(sBh, sBl, vh, vl, k0, tid);
        __syncthreads();
        mma_compute<1, 8>(sAh, sAl, sBh, sBl, wrow, wcol, lane, acc);
    }

    const int b = bz >> 3, hh = bz & 7;
    const int r0 = tile_m + wrow + (lane >> 2);
    const int c0 = (lane & 3) * 2;
    #pragma unroll
    for (int hf = 0; hf < 2; hf++) {
        int t = r0 + hf * 8;
        size_t rowbase = ((size_t)b * TT + t) * DDIM + hh * DKH;
        #pragma unroll
        for (int nf = 0; nf < 8; nf++) {
            int dk = c0 + nf * 8;
            float v0 = acc[0][nf][hf * 2];
            float v1 = acc[0][nf][hf * 2 + 1];
            __nv_bfloat16 h0, l0, h1, l1;
            split_hl(v0, h0, l0);
            split_hl(v1, h1, l1);
            *(u32*)&g_ch[rowbase + dk] = pack2(h0, h1);
            *(u32*)&g_cl[rowbase + dk] = pack2(l0, l1);
        }
    }
}

// ---------------- outproj: out = ctx @ Wo^T + bo -> fp32 d_out --------------
__global__ __launch_bounds__(256, 2) void outproj_mma(const float* __restrict__ bo,
                                                      float* __restrict__ out)
{
    __shared__ __nv_bfloat16 sAh[128][BKP], sAl[128][BKP];
    __shared__ __nv_bfloat16 sBh[128][BKP], sBl[128][BKP];
    const int tid = threadIdx.x, lane = tid & 31, wid = tid >> 5;
    const int wrow = (wid >> 1) * 32, wcol = (wid & 1) * 64;
    const int tile_m = blockIdx.y * 128, tile_n = blockIdx.x * 128;

    float acc[2][8][4] = {};
    for (int k0 = 0; k0 < DDIM; k0 += 32) {
        __syncthreads();
        load_hl<128>(sAh, sAl, g_ch, g_cl, DDIM, tile_m, k0, tid);
        load_hl<128>(sBh, sBl, g_wh[3], g_wl[3], DDIM, tile_n, k0, tid);
        __syncthreads();
        mma_compute<2, 8>(sAh, sAl, sBh, sBl, wrow, wcol, lane, acc);
    }

    const int r0 = tile_m + wrow + (lane >> 2);
    const int c0 = tile_n + wcol + (lane & 3) * 2;
    #pragma unroll
    for (int mf = 0; mf < 2; mf++)
        #pragma unroll
        for (int hf = 0; hf < 2; hf++) {
            int m = r0 + mf * 16 + hf * 8;
            #pragma unroll
            for (int nf = 0; nf < 8; nf++) {
                int n = c0 + nf * 8;
                float2 v;
                v.x = acc[mf][nf][hf * 2]     + bo[n];
                v.y = acc[mf][nf][hf * 2 + 1] + bo[n + 1];
                *(float2*)&out[(size_t)m * DDIM + n] = v;
            }
        }
}

// -----------------------------------------------------------------------------
extern "C" void kernel_launch(void* const* d_in, const int* in_sizes, int n_in,
                              void* d_out, int out_size)
{
    const float* key   = (const float*)d_in[0];
    const float* value = (const float*)d_in[1];
    const float* query = (const float*)d_in[2];
    const int*   mask  = (const int*)d_in[3];
    const float* Wk = (const float*)d_in[4];
    const float* bk = (const float*)d_in[5];
    const float* Wv = (const float*)d_in[6];
    const float* bv = (const float*)d_in[7];
    const float* Wq = (const float*)d_in[8];
    const float* bq = (const float*)d_in[9];
    const float* Wo = (const float*)d_in[10];
    const float* bo = (const float*)d_in[11];

    float* out = (float*)d_out;
    float* ctx_out = out;                            // [B, T, D]
    float* aw_out  = out + (size_t)BB * TT * DDIM;   // [B, H, T, T]

    // conversions
    cvt_x_kernel<<<SZX / 256, 256>>>(query, 0);
    cvt_x_kernel<<<SZX / 256, 256>>>(key, 1);
    cvt_x_kernel<<<SZX / 256, 256>>>(value, 2);
    cvt_w_kernel<<<(DDIM * DDIM) / 256, 256>>>(Wq, 0);
    cvt_w_kernel<<<(DDIM * DDIM) / 256, 256>>>(Wk, 1);
    cvt_w_kernel<<<(DDIM * DDIM) / 256, 256>>>(Wv, 2);
    cvt_w_kernel<<<(DDIM * DDIM) / 256, 256>>>(Wo, 3);
    cvt_mask_kernel<<<((size_t)BB * TT * TT) / 256, 256>>>(mask);

    // QKV projections
    dim3 gp(DDIM / 128, (BB * TT) / 128);
    proj_mma<<<gp, 256>>>(0, 0, bq, 0);
    proj_mma<<<gp, 256>>>(1, 1, bk, 1);
    proj_mma<<<gp, 256>>>(2, 2, bv, 2);

    // energy -> exp'd, masked, unnormalized probabilities in aw region
    energy_mma<<<dim3(TT / 128, TT / 128, BB * HH), 256>>>(aw_out);

    // deterministic per-row normalization
    norm_kernel<<<BB * HH * TT, 256>>>(aw_out);

    // context = aw @ v
    av_mma<<<dim3(1, TT / 128, BB * HH), 256>>>(aw_out);

    // output projection
    outproj_mma<<<gp, 256>>>(bo, ctx_out);
}

// round 5
// speedup vs baseline: 2.6903x; 1.2518x over previous
#include <cuda_runtime.h>
#include <cuda_bf16.h>
#include <cstdint>

typedef unsigned int u32;

#define BB 4
#define TT 2048
#define DDIM 512
#define HH 8
#define DKH 64

#define SZQ ((size_t)BB * HH * TT * DKH)   // 4,194,304
#define SZX ((size_t)BB * TT * DDIM)       // 4,194,304

// ---------------- scratch (__device__ globals; no allocation) ----------------
__device__ float g_q[SZQ];                        // [B,H,T,DK] fp32
__device__ float g_k[SZQ];                        // [B,H,T,DK] fp32
__device__ float g_vt[SZQ];                       // [B,H,DK,T] fp32 (transposed)
__device__ float g_ctx[SZX];                      // [B,T,D] fp32
__device__ float g_inv[(size_t)BB * HH * TT];     // per-row 1/sum
__device__ u32 g_mbits[(size_t)BB * TT * (TT / 32)];  // packed mask bits

// ---------------- helpers ----------------
__device__ __forceinline__ u32 smem_u32(const void* p) {
    u32 a;
    asm("{ .reg .u64 t; cvta.to.shared.u64 t, %1; cvt.u32.u64 %0, t; }" : "=r"(a) : "l"(p));
    return a;
}
__device__ __forceinline__ void split_hl(float v, __nv_bfloat16& h, __nv_bfloat16& l) {
    h = __float2bfloat16(v);
    l = __float2bfloat16(v - __bfloat162float(h));
}
__device__ __forceinline__ u32 pack2(__nv_bfloat16 a, __nv_bfloat16 b) {
    return (u32)__bfloat16_as_ushort(a) | ((u32)__bfloat16_as_ushort(b) << 16);
}
__device__ __forceinline__ void ldsm_x4(u32& r0, u32& r1, u32& r2, u32& r3, u32 addr) {
    asm volatile("ldmatrix.sync.aligned.m8n8.x4.shared.b16 {%0,%1,%2,%3}, [%4];"
                 : "=r"(r0), "=r"(r1), "=r"(r2), "=r"(r3) : "r"(addr));
}
__device__ __forceinline__ void mma16816(float* c, const u32* a, u32 b0, u32 b1) {
    asm volatile(
        "mma.sync.aligned.m16n8k16.row.col.f32.bf16.bf16.f32 "
        "{%0,%1,%2,%3}, {%4,%5,%6,%7}, {%8,%9}, {%0,%1,%2,%3};"
        : "+f"(c[0]), "+f"(c[1]), "+f"(c[2]), "+f"(c[3])
        : "r"(a[0]), "r"(a[1]), "r"(a[2]), "r"(a[3]), "r"(b0), "r"(b1));
}

// fp32 source [rows][ld] -> bf16 hi/lo smem tiles. W4 float4-groups per row.
template <int ROWS, int W4, int STRIDE>
__device__ __forceinline__ void load_f32_hl(
    __nv_bfloat16 (*sh)[STRIDE], __nv_bfloat16 (*sl)[STRIDE],
    const float* __restrict__ g, size_t ld, size_t row0, int k0, int tid)
{
    #pragma unroll
    for (int i = tid; i < ROWS * W4; i += 256) {
        int r = i / W4, c = i % W4;
        float4 v = *(const float4*)&g[(row0 + (size_t)r) * ld + k0 + c * 4];
        __nv_bfloat16 h0, l0, h1, l1, h2, l2, h3, l3;
        split_hl(v.x, h0, l0); split_hl(v.y, h1, l1);
        split_hl(v.z, h2, l2); split_hl(v.w, h3, l3);
        *(uint2*)&sh[r][c * 4] = make_uint2(pack2(h0, h1), pack2(h2, h3));
        *(uint2*)&sl[r][c * 4] = make_uint2(pack2(l0, l1), pack2(l2, l3));
    }
}

// warp-MMA over one 32-wide K slab, bf16x3 emulation (3 MMA terms)
template <int MF, int NF, int AS, int BS>
__device__ __forceinline__ void mma_hl(
    const __nv_bfloat16 (*Ah)[AS], const __nv_bfloat16 (*Al)[AS],
    const __nv_bfloat16 (*Bh)[BS], const __nv_bfloat16 (*Bl)[BS],
    int wrow, int wcol, int lane, int kA, int kB, float acc[MF][NF][4])
{
    const int arow = wrow + (lane & 15);
    const int akh = (lane >> 4) << 3;
    const int brow = wcol + (lane & 7) + ((lane & 16) >> 1);
    const int bkh = (lane & 8);
    #pragma unroll
    for (int ks = 0; ks < 32; ks += 16) {
        u32 ah[MF][4], al[MF][4];
        #pragma unroll
        for (int mf = 0; mf < MF; mf++) {
            ldsm_x4(ah[mf][0], ah[mf][1], ah[mf][2], ah[mf][3],
                    smem_u32(&Ah[arow + mf * 16][kA + ks + akh]));
            ldsm_x4(al[mf][0], al[mf][1], al[mf][2], al[mf][3],
                    smem_u32(&Al[arow + mf * 16][kA + ks + akh]));
        }
        #pragma unroll
        for (int np = 0; np < NF / 2; np++) {
            u32 bh0, bh1, bh2, bh3, bl0, bl1, bl2, bl3;
            ldsm_x4(bh0, bh1, bh2, bh3, smem_u32(&Bh[brow + np * 16][kB + ks + bkh]));
            ldsm_x4(bl0, bl1, bl2, bl3, smem_u32(&Bl[brow + np * 16][kB + ks + bkh]));
            #pragma unroll
            for (int mf = 0; mf < MF; mf++) {
                mma16816(acc[mf][2 * np],     ah[mf], bh0, bh1);
                mma16816(acc[mf][2 * np],     ah[mf], bl0, bl1);
                mma16816(acc[mf][2 * np],     al[mf], bh0, bh1);
                mma16816(acc[mf][2 * np + 1], ah[mf], bh2, bh3);
                mma16816(acc[mf][2 * np + 1], ah[mf], bl2, bl3);
                mma16816(acc[mf][2 * np + 1], al[mf], bh2, bh3);
            }
        }
    }
}

// ---------------- mask bit packing ----------------
__global__ __launch_bounds__(256) void cvt_mask_kernel(const int* __restrict__ mask)
{
    size_t i = (size_t)blockIdx.x * 256 + threadIdx.x;
    u32 bit = (mask[i] != 0) ? 1u : 0u;
    u32 word = __ballot_sync(0xffffffffu, bit);
    if ((threadIdx.x & 31) == 0) g_mbits[i >> 5] = word;
}

// ---------------- proj: out = X @ W^T + b -> q/k fp32 [B,H,T,DK], vt [B,H,DK,T]
__global__ __launch_bounds__(256, 2) void proj_mma(const float* __restrict__ X,
                                                   const float* __restrict__ W,
                                                   const float* __restrict__ bias, int dst)
{
    __shared__ __nv_bfloat16 sAh[128][40], sAl[128][40];
    __shared__ __nv_bfloat16 sBh[128][40], sBl[128][40];
    const int tid = threadIdx.x, lane = tid & 31, wid = tid >> 5;
    const int wrow = (wid >> 1) * 32, wcol = (wid & 1) * 64;
    const int tile_m = blockIdx.y * 128, tile_n = blockIdx.x * 128;

    float acc[2][8][4] = {};
    for (int k0 = 0; k0 < DDIM; k0 += 32) {
        __syncthreads();
        load_f32_hl<128, 8, 40>(sAh, sAl, X, DDIM, tile_m, k0, tid);
        load_f32_hl<128, 8, 40>(sBh, sBl, W, DDIM, tile_n, k0, tid);
        __syncthreads();
        mma_hl<2, 8, 40, 40>(sAh, sAl, sBh, sBl, wrow, wcol, lane, 0, 0, acc);
    }

    float* dq = (dst == 0) ? g_q : g_k;
    const int r0 = tile_m + wrow + (lane >> 2);
    const int c0 = tile_n + wcol + (lane & 3) * 2;
    #pragma unroll
    for (int mf = 0; mf < 2; mf++)
        #pragma unroll
        for (int hf = 0; hf < 2; hf++) {
            int m = r0 + mf * 16 + hf * 8;
            int b = m >> 11, t = m & (TT - 1);
            #pragma unroll
            for (int nf = 0; nf < 8; nf++) {
                int n = c0 + nf * 8;
                float v0 = acc[mf][nf][hf * 2]     + bias[n];
                float v1 = acc[mf][nf][hf * 2 + 1] + bias[n + 1];
                int hh = n >> 6, dk = n & 63;
                if (dst == 2) {
                    size_t base = ((size_t)(b * HH + hh) * DKH + dk) * TT + t;
                    g_vt[base] = v0;
                    g_vt[base + TT] = v1;
                } else {
                    size_t idx = ((size_t)(b * HH + hh) * TT + t) * DKH + dk;
                    *(float2*)&dq[idx] = make_float2(v0, v1);
                }
            }
        }
}

// ---------------- fused: S=QK^T/8 -> exp/mask -> p(unnorm)->aw; ctx=(p@v)/sum
// grid (16 tile_m, 32 bh), 256 thr, dynamic smem
__global__ __launch_bounds__(256, 2) void fused_attn(float* __restrict__ aw)
{
    extern __shared__ __nv_bfloat16 dyn[];
    __nv_bfloat16 (*sQh)[72] = (__nv_bfloat16 (*)[72])(dyn);
    __nv_bfloat16 (*sQl)[72] = (__nv_bfloat16 (*)[72])(dyn + 9216);
    __nv_bfloat16 (*sKh)[72] = (__nv_bfloat16 (*)[72])(dyn + 18432);
    __nv_bfloat16 (*sKl)[72] = (__nv_bfloat16 (*)[72])(dyn + 23040);
    __nv_bfloat16 (*sVh)[72] = (__nv_bfloat16 (*)[72])(dyn + 27648);
    __nv_bfloat16 (*sVl)[72] = (__nv_bfloat16 (*)[72])(dyn + 32256);
    __nv_bfloat16 (*sPh)[40] = (__nv_bfloat16 (*)[40])(dyn + 36864);
    __nv_bfloat16 (*sPl)[40] = (__nv_bfloat16 (*)[40])(dyn + 41984);

    const int tid = threadIdx.x, lane = tid & 31, wid = tid >> 5;
    const int wrow = wid * 16;
    const int tile_m = blockIdx.x * 128;
    const int bz = blockIdx.y;
    const int b = bz >> 3, hh = bz & 7;
    const float* qh = g_q + (size_t)bz * TT * DKH;
    const float* kh = g_k + (size_t)bz * TT * DKH;
    const float* vt = g_vt + (size_t)bz * DKH * TT;

    load_f32_hl<128, 16, 72>(sQh, sQl, qh, DKH, tile_m, 0, tid);

    float acc_av[1][8][4] = {};
    float rs[2] = {0.0f, 0.0f};
    const int rq = (lane >> 2);
    const int cq = (lane & 3) * 2;

    for (int kt = 0; kt < 32; kt++) {
        __syncthreads();
        load_f32_hl<64, 16, 72>(sKh, sKl, kh, DKH, kt * 64, 0, tid);
        load_f32_hl<64, 16, 72>(sVh, sVl, vt, TT, 0, kt * 64, tid);
        __syncthreads();

        float acc_s[1][8][4] = {};
        mma_hl<1, 8, 72, 72>(sQh, sQl, sKh, sKl, wrow, 0, lane, 0, 0, acc_s);
        mma_hl<1, 8, 72, 72>(sQh, sQl, sKh, sKl, wrow, 0, lane, 32, 32, acc_s);

        // epilogue: exp + mask, write unnormalized p, accumulate row sums
        #pragma unroll
        for (int hf = 0; hf < 2; hf++) {
            int tq = tile_m + wrow + rq + hf * 8;
            const u32* mrow = g_mbits + ((size_t)b * TT + tq) * (TT / 32);
            float* prow = aw + ((size_t)bz * TT + tq) * TT;
            #pragma unroll
            for (int nf = 0; nf < 8; nf++) {
                int tk = kt * 64 + cq + nf * 8;
                u32 w = mrow[tk >> 5];
                int sh = tk & 31;
                float e0 = acc_s[0][nf][hf * 2]     * 0.125f;
                float e1 = acc_s[0][nf][hf * 2 + 1] * 0.125f;
                float p0 = ((w >> sh) & 1u)       ? __expf(e0) : 0.0f;
                float p1 = ((w >> (sh + 1)) & 1u) ? __expf(e1) : 0.0f;
                rs[hf] += p0 + p1;
                *(float2*)&prow[tk] = make_float2(p0, p1);
                acc_s[0][nf][hf * 2]     = p0;
                acc_s[0][nf][hf * 2 + 1] = p1;
            }
        }

        // AV accumulate: ctx += p @ v (two 32-wide slabs)
        #pragma unroll
        for (int cb = 0; cb < 2; cb++) {
            __syncthreads();
            #pragma unroll
            for (int hf = 0; hf < 2; hf++) {
                int r = wrow + rq + hf * 8;
                #pragma unroll
                for (int nf4 = 0; nf4 < 4; nf4++) {
                    int nf = cb * 4 + nf4;
                    __nv_bfloat16 h0, l0, h1, l1;
                    split_hl(acc_s[0][nf][hf * 2], h0, l0);
                    split_hl(acc_s[0][nf][hf * 2 + 1], h1, l1);
                    int lc = cq + nf4 * 8;
                    *(u32*)&sPh[r][lc] = pack2(h0, h1);
                    *(u32*)&sPl[r][lc] = pack2(l0, l1);
                }
            }
            __syncthreads();
            mma_hl<1, 8, 40, 72>(sPh, sPl, sVh, sVl, wrow, 0, lane, 0, cb * 32, acc_av);
        }
    }

    // deterministic row-sum reduction across the 4 lanes sharing each row
    #pragma unroll
    for (int hf = 0; hf < 2; hf++) {
        rs[hf] += __shfl_xor_sync(0xffffffffu, rs[hf], 1);
        rs[hf] += __shfl_xor_sync(0xffffffffu, rs[hf], 2);
    }
    float inv0 = 1.0f / rs[0], inv1 = 1.0f / rs[1];
    if ((lane & 3) == 0) {
        g_inv[(size_t)bz * TT + tile_m + wrow + rq]     = inv0;
        g_inv[(size_t)bz * TT + tile_m + wrow + rq + 8] = inv1;
    }

    // write normalized ctx
    #pragma unroll
    for (int hf = 0; hf < 2; hf++) {
        float inv = hf ? inv1 : inv0;
        int tq = tile_m + wrow + rq + hf * 8;
        float* crow = g_ctx + ((size_t)b * TT + tq) * DDIM + hh * DKH;
        #pragma unroll
        for (int nf = 0; nf < 8; nf++) {
            int dk = cq + nf * 8;
            *(float2*)&crow[dk] = make_float2(acc_av[0][nf][hf * 2] * inv,
                                              acc_av[0][nf][hf * 2 + 1] * inv);
        }
    }
}

// ---------------- normalize: aw[row] *= g_inv[row] ----------------
__global__ __launch_bounds__(256) void norm_kernel(float* __restrict__ aw)
{
    size_t row = blockIdx.x;
    float inv = g_inv[row];
    float4* p = (float4*)(aw + row * (size_t)TT);
    int tid = threadIdx.x;
    float4 v0 = p[tid], v1 = p[tid + 256];
    v0.x *= inv; v0.y *= inv; v0.z *= inv; v0.w *= inv;
    v1.x *= inv; v1.y *= inv; v1.z *= inv; v1.w *= inv;
    p[tid] = v0;
    p[tid + 256] = v1;
}

// ---------------- outproj: out = ctx @ Wo^T + bo -> fp32 d_out --------------
__global__ __launch_bounds__(256, 2) void outproj_mma(const float* __restrict__ Wo,
                                                      const float* __restrict__ bo,
                                                      float* __restrict__ out)
{
    __shared__ __nv_bfloat16 sAh[128][40], sAl[128][40];
    __shared__ __nv_bfloat16 sBh[128][40], sBl[128][40];
    const int tid = threadIdx.x, lane = tid & 31, wid = tid >> 5;
    const int wrow = (wid >> 1) * 32, wcol = (wid & 1) * 64;
    const int tile_m = blockIdx.y * 128, tile_n = blockIdx.x * 128;

    float acc[2][8][4] = {};
    for (int k0 = 0; k0 < DDIM; k0 += 32) {
        __syncthreads();
        load_f32_hl<128, 8, 40>(sAh, sAl, g_ctx, DDIM, tile_m, k0, tid);
        load_f32_hl<128, 8, 40>(sBh, sBl, Wo, DDIM, tile_n, k0, tid);
        __syncthreads();
        mma_hl<2, 8, 40, 40>(sAh, sAl, sBh, sBl, wrow, wcol, lane, 0, 0, acc);
    }

    const int r0 = tile_m + wrow + (lane >> 2);
    const int c0 = tile_n + wcol + (lane & 3) * 2;
    #pragma unroll
    for (int mf = 0; mf < 2; mf++)
        #pragma unroll
        for (int hf = 0; hf < 2; hf++) {
            int m = r0 + mf * 16 + hf * 8;
            #pragma unroll
            for (int nf = 0; nf < 8; nf++) {
                int n = c0 + nf * 8;
                *(float2*)&out[(size_t)m * DDIM + n] =
                    make_float2(acc[mf][nf][hf * 2] + bo[n],
                                acc[mf][nf][hf * 2 + 1] + bo[n + 1]);
            }
        }
}

// -----------------------------------------------------------------------------
extern "C" void kernel_launch(void* const* d_in, const int* in_sizes, int n_in,
                              void* d_out, int out_size)
{
    const float* key   = (const float*)d_in[0];
    const float* value = (const float*)d_in[1];
    const float* query = (const float*)d_in[2];
    const int*   mask  = (const int*)d_in[3];
    const float* Wk = (const float*)d_in[4];
    const float* bk = (const float*)d_in[5];
    const float* Wv = (const float*)d_in[6];
    const float* bv = (const float*)d_in[7];
    const float* Wq = (const float*)d_in[8];
    const float* bq = (const float*)d_in[9];
    const float* Wo = (const float*)d_in[10];
    const float* bo = (const float*)d_in[11];

    float* out = (float*)d_out;
    float* ctx_out = out;                            // [B, T, D]
    float* aw_out  = out + (size_t)BB * TT * DDIM;   // [B, H, T, T]

    cvt_mask_kernel<<<((size_t)BB * TT * TT) / 256, 256>>>(mask);

    dim3 gp(DDIM / 128, (BB * TT) / 128);
    proj_mma<<<gp, 256>>>(query, Wq, bq, 0);
    proj_mma<<<gp, 256>>>(key,   Wk, bk, 1);
    proj_mma<<<gp, 256>>>(value, Wv, bv, 2);

    // fused attention: dynamic smem 94,208 B
    const int FUSED_SMEM = 94208;
    cudaFuncSetAttribute(fused_attn, cudaFuncAttributeMaxDynamicSharedMemorySize,
                         FUSED_SMEM);
    fused_attn<<<dim3(TT / 128, BB * HH), 256, FUSED_SMEM>>>(aw_out);

    norm_kernel<<<BB * HH * TT, 256>>>(aw_out);

    outproj_mma<<<gp, 256>>>(Wo, bo, ctx_out);
}